// round 1
// baseline (speedup 1.0000x reference)
#include <cuda_runtime.h>
#include <cuda_bf16.h>
#include <cstdint>

// Problem constants (match reference)
#define N_SEL   192
#define N_PTS   2048
#define C_IN    256
#define C_OUT   256
#define N_TILES 8

#define BM 128
#define BN 128
#define BK 8
#define LDA_S (BM + 4)   // 132, multiple of 4 -> float4-aligned rows

__global__ __launch_bounds__(256, 2)
void adaptive_linear_kernel(const float* __restrict__ x,
                            const float* __restrict__ weight,
                            const float* __restrict__ bias,
                            const int*   __restrict__ indices,
                            const int*   __restrict__ t_ptr,
                            float*       __restrict__ out) {
    const int n     = blockIdx.z;           // selected channel 0..191
    const int tileM = blockIdx.y;           // 0..15
    const int tileN = blockIdx.x;           // 0..1

    const int t   = (t_ptr != nullptr) ? *t_ptr : 3;   // little-endian low word; works for i32/i64
    const int idx = indices[n];

    const float* A = x + (size_t)n * N_PTS * C_IN;                               // [2048, 256] row-major (M, K)
    const float* B = weight + (((size_t)idx * N_TILES + t) * C_IN) * C_OUT;      // [256, 256] row-major (K, N)
    const float* bb = bias + ((size_t)idx * N_TILES + t) * C_OUT;                // [256]

    const int m0 = tileM * BM;
    const int n0 = tileN * BN;

    __shared__ float As[BK][LDA_S];  // transposed: As[k][m]
    __shared__ float Bs[BK][BN];     // Bs[k][n]

    const int tid = threadIdx.x;     // 0..255
    const int tx  = tid & 15;        // 0..15  -> N columns
    const int ty  = tid >> 4;        // 0..15  -> M rows

    // Global-load assignments
    const int arow  = tid >> 1;          // 0..127
    const int acol4 = (tid & 1) * 4;     // 0 or 4 (within BK=8)
    const int brow  = tid >> 5;          // 0..7
    const int bcol  = (tid & 31) * 4;    // 0..124

    float acc[8][8];
    #pragma unroll
    for (int i = 0; i < 8; i++)
        #pragma unroll
        for (int j = 0; j < 8; j++)
            acc[i][j] = 0.0f;

    for (int k0 = 0; k0 < C_IN; k0 += BK) {
        // ---- load A tile (128 x 8), transpose into As[k][m] ----
        {
            const float4 av = *reinterpret_cast<const float4*>(
                A + (size_t)(m0 + arow) * C_IN + k0 + acol4);
            As[acol4 + 0][arow] = av.x;
            As[acol4 + 1][arow] = av.y;
            As[acol4 + 2][arow] = av.z;
            As[acol4 + 3][arow] = av.w;
        }
        // ---- load B tile (8 x 128) ----
        {
            const float4 bv = *reinterpret_cast<const float4*>(
                B + (size_t)(k0 + brow) * C_OUT + n0 + bcol);
            *reinterpret_cast<float4*>(&Bs[brow][bcol]) = bv;
        }
        __syncthreads();

        #pragma unroll
        for (int kk = 0; kk < BK; kk++) {
            float a[8], b[8];
            {
                float4 a0 = *reinterpret_cast<const float4*>(&As[kk][ty * 4]);
                float4 a1 = *reinterpret_cast<const float4*>(&As[kk][64 + ty * 4]);
                a[0] = a0.x; a[1] = a0.y; a[2] = a0.z; a[3] = a0.w;
                a[4] = a1.x; a[5] = a1.y; a[6] = a1.z; a[7] = a1.w;
                float4 b0 = *reinterpret_cast<const float4*>(&Bs[kk][tx * 4]);
                float4 b1 = *reinterpret_cast<const float4*>(&Bs[kk][64 + tx * 4]);
                b[0] = b0.x; b[1] = b0.y; b[2] = b0.z; b[3] = b0.w;
                b[4] = b1.x; b[5] = b1.y; b[6] = b1.z; b[7] = b1.w;
            }
            #pragma unroll
            for (int i = 0; i < 8; i++)
                #pragma unroll
                for (int j = 0; j < 8; j++)
                    acc[i][j] = fmaf(a[i], b[j], acc[i][j]);
        }
        __syncthreads();
    }

    // ---- epilogue: add bias, write out ----
    const int c0 = n0 + tx * 4;
    const int c1 = n0 + 64 + tx * 4;
    const float4 bv0 = *reinterpret_cast<const float4*>(bb + c0);
    const float4 bv1 = *reinterpret_cast<const float4*>(bb + c1);

    float* Out = out + (size_t)n * N_PTS * C_OUT;

    #pragma unroll
    for (int i = 0; i < 8; i++) {
        const int r = (i < 4) ? (m0 + ty * 4 + i) : (m0 + 64 + ty * 4 + (i - 4));
        float4 o0, o1;
        o0.x = acc[i][0] + bv0.x; o0.y = acc[i][1] + bv0.y;
        o0.z = acc[i][2] + bv0.z; o0.w = acc[i][3] + bv0.w;
        o1.x = acc[i][4] + bv1.x; o1.y = acc[i][5] + bv1.y;
        o1.z = acc[i][6] + bv1.z; o1.w = acc[i][7] + bv1.w;
        *reinterpret_cast<float4*>(Out + (size_t)r * C_OUT + c0) = o0;
        *reinterpret_cast<float4*>(Out + (size_t)r * C_OUT + c1) = o1;
    }
}

extern "C" void kernel_launch(void* const* d_in, const int* in_sizes, int n_in,
                              void* d_out, int out_size) {
    const float* x       = (const float*)d_in[0];
    const float* weight  = (const float*)d_in[1];
    const float* bias    = (const float*)d_in[2];
    const int*   indices = (const int*)d_in[3];
    const int*   t_ptr   = (n_in > 4) ? (const int*)d_in[4] : nullptr;
    float*       out     = (float*)d_out;

    dim3 grid(BN == 128 ? C_OUT / BN : 1, N_PTS / BM, N_SEL);  // (2, 16, 192)
    dim3 block(256);
    adaptive_linear_kernel<<<grid, block>>>(x, weight, bias, indices, t_ptr, out);
}

// round 3
// speedup vs baseline: 1.8334x; 1.8334x over previous
#include <cuda_runtime.h>
#include <cuda_bf16.h>
#include <cstdint>

#define N_SEL   192
#define N_PTS   2048
#define C_IN    256
#define C_OUT   256
#define N_TILES 8

#define BM 128
#define BN 128
#define BK 32

// gathered, transposed, bf16-split weights: [n_sel][N=C_OUT][K=C_IN]
__device__ __nv_bfloat16 g_wt_h[(size_t)N_SEL * C_OUT * C_IN];
__device__ __nv_bfloat16 g_wt_l[(size_t)N_SEL * C_OUT * C_IN];

__device__ __forceinline__ uint32_t smem_u32(const void* p) {
    uint32_t a;
    asm("{ .reg .u64 t; cvta.to.shared.u64 t, %1; cvt.u32.u64 %0, t; }" : "=r"(a) : "l"(p));
    return a;
}

__device__ __forceinline__ void bf16_split2(float a, float b, uint32_t& h, uint32_t& l) {
    __nv_bfloat16 ha = __float2bfloat16_rn(a);
    __nv_bfloat16 hb = __float2bfloat16_rn(b);
    __nv_bfloat16 la = __float2bfloat16_rn(a - __bfloat162float(ha));
    __nv_bfloat16 lb = __float2bfloat16_rn(b - __bfloat162float(hb));
    h = (uint32_t)__bfloat16_as_ushort(ha) | ((uint32_t)__bfloat16_as_ushort(hb) << 16);
    l = (uint32_t)__bfloat16_as_ushort(la) | ((uint32_t)__bfloat16_as_ushort(lb) << 16);
}

__device__ __forceinline__ void ldmx4(uint32_t addr, uint32_t& r0, uint32_t& r1,
                                      uint32_t& r2, uint32_t& r3) {
    asm volatile("ldmatrix.sync.aligned.m8n8.x4.shared.b16 {%0,%1,%2,%3}, [%4];"
                 : "=r"(r0), "=r"(r1), "=r"(r2), "=r"(r3) : "r"(addr));
}

__device__ __forceinline__ void mma_bf16(float* c, const uint32_t* a, const uint32_t* b) {
    asm volatile("mma.sync.aligned.m16n8k16.row.col.f32.bf16.bf16.f32 "
                 "{%0,%1,%2,%3}, {%4,%5,%6,%7}, {%8,%9}, {%0,%1,%2,%3};"
                 : "+f"(c[0]), "+f"(c[1]), "+f"(c[2]), "+f"(c[3])
                 : "r"(a[0]), "r"(a[1]), "r"(a[2]), "r"(a[3]), "r"(b[0]), "r"(b[1]));
}

// ---------------- kernel 1: gather + transpose + bf16 split of W ----------------
__global__ void wt_prep_kernel(const float* __restrict__ weight,
                               const int* __restrict__ indices,
                               const int* __restrict__ t_ptr) {
    const int n = blockIdx.z;
    const int t = (t_ptr != nullptr) ? *t_ptr : 3;
    const int idx = indices[n];
    const float* W = weight + (((size_t)idx * N_TILES + t) * C_IN) * C_OUT; // [K][N]

    __shared__ float tile[32][33];
    const int tx = threadIdx.x;   // 0..31
    const int ty = threadIdx.y;   // 0..7
    const int kt = blockIdx.y * 32;
    const int nt = blockIdx.x * 32;

    #pragma unroll
    for (int j = 0; j < 4; j++) {
        const int k = kt + ty + j * 8;
        tile[ty + j * 8][tx] = W[(size_t)k * C_OUT + nt + tx];
    }
    __syncthreads();

    __nv_bfloat16* oh = g_wt_h + (size_t)n * C_OUT * C_IN;
    __nv_bfloat16* ol = g_wt_l + (size_t)n * C_OUT * C_IN;
    #pragma unroll
    for (int j = 0; j < 4; j++) {
        const int nn = nt + ty + j * 8;
        const float v = tile[tx][ty + j * 8];   // = W[kt+tx][nn]
        const __nv_bfloat16 h = __float2bfloat16_rn(v);
        const __nv_bfloat16 l = __float2bfloat16_rn(v - __bfloat162float(h));
        oh[(size_t)nn * C_IN + kt + tx] = h;
        ol[(size_t)nn * C_IN + kt + tx] = l;
    }
}

// ---------------- kernel 2: bf16 mma.sync GEMM (3-term split) ----------------
// SMEM: 4 tiles of 128 rows x 80 bytes (32 bf16 + 8 pad) + 256-float bias
#define ROWB  80
#define SM_AH 0
#define SM_AL (SM_AH + BM * ROWB)
#define SM_BH (SM_AL + BM * ROWB)
#define SM_BL (SM_BH + BN * ROWB)
#define SM_BS (SM_BL + BN * ROWB)

__global__ __launch_bounds__(256)
void gemm_bf16_kernel(const float* __restrict__ x,
                      const float* __restrict__ bias,
                      const int* __restrict__ indices,
                      const int* __restrict__ t_ptr,
                      float* __restrict__ out) {
    __shared__ __align__(16) unsigned char smem[SM_BS + C_OUT * 4];
    const uint32_t sa = smem_u32(smem);

    const int tid  = threadIdx.x;
    const int lane = tid & 31;
    const int wid  = tid >> 5;

    const int n_sel  = blockIdx.z;
    const int m0     = blockIdx.x * BM;
    const int n_base = blockIdx.y * BN;
    const int t   = (t_ptr != nullptr) ? *t_ptr : 3;
    const int idx = indices[n_sel];

    const float* A = x + (size_t)n_sel * N_PTS * C_IN + (size_t)m0 * C_IN;
    const __nv_bfloat16* BH = g_wt_h + (size_t)n_sel * C_OUT * C_IN + (size_t)n_base * C_IN;
    const __nv_bfloat16* BL = g_wt_l + (size_t)n_sel * C_OUT * C_IN + (size_t)n_base * C_IN;

    // bias -> smem (fp32)
    float* bs = (float*)(smem + SM_BS);
    if (tid < C_OUT) bs[tid] = bias[((size_t)idx * N_TILES + t) * C_OUT + n_base + tid];

    // warp tiling: 2 m-warps x 4 n-warps; warp tile 64x32
    const int m_off = (wid >> 2) * 64;
    const int n_off = (wid & 3) * 32;

    float acc[4][4][4];
    #pragma unroll
    for (int i = 0; i < 4; i++)
        #pragma unroll
        for (int j = 0; j < 4; j++)
            #pragma unroll
            for (int q = 0; q < 4; q++)
                acc[i][j][q] = 0.0f;

    // per-thread load assignments
    const int arow  = tid >> 1;         // 0..127
    const int ahalf = tid & 1;          // 16-float half of the 32-col slab

    for (int k0 = 0; k0 < C_IN; k0 += BK) {
        // ---- A slab: 128x32 fp32 -> bf16 hi/lo ----
        {
            const float* src = A + (size_t)arow * C_IN + k0 + ahalf * 16;
            uint32_t h[8], l[8];
            #pragma unroll
            for (int v = 0; v < 4; v++) {
                const float4 f = *reinterpret_cast<const float4*>(src + v * 4);
                bf16_split2(f.x, f.y, h[v * 2], l[v * 2]);
                bf16_split2(f.z, f.w, h[v * 2 + 1], l[v * 2 + 1]);
            }
            const uint32_t so = (uint32_t)(arow * ROWB + ahalf * 32);
            *reinterpret_cast<uint4*>(smem + SM_AH + so)      = make_uint4(h[0], h[1], h[2], h[3]);
            *reinterpret_cast<uint4*>(smem + SM_AH + so + 16) = make_uint4(h[4], h[5], h[6], h[7]);
            *reinterpret_cast<uint4*>(smem + SM_AL + so)      = make_uint4(l[0], l[1], l[2], l[3]);
            *reinterpret_cast<uint4*>(smem + SM_AL + so + 16) = make_uint4(l[4], l[5], l[6], l[7]);
        }
        // ---- B slab: 128 n-rows x 32 k bf16 (hi & lo), already split ----
        #pragma unroll
        for (int it = 0; it < 2; it++) {
            const int v   = tid + it * 256;      // 0..511
            const int r   = v >> 2;              // n row 0..127
            const int seg = v & 3;               // 8-bf16 segment
            const size_t go = (size_t)r * C_IN + k0 + seg * 8;
            const uint32_t so = (uint32_t)(r * ROWB + seg * 16);
            *reinterpret_cast<uint4*>(smem + SM_BH + so) =
                *reinterpret_cast<const uint4*>(BH + go);
            *reinterpret_cast<uint4*>(smem + SM_BL + so) =
                *reinterpret_cast<const uint4*>(BL + go);
        }
        __syncthreads();

        // ---- compute: two k-steps of 16 ----
        #pragma unroll
        for (int ks = 0; ks < BK; ks += 16) {
            uint32_t bh[4][2], bl[4][2];
            #pragma unroll
            for (int p = 0; p < 2; p++) {
                const int quad = lane >> 3;
                const int rowB = n_off + p * 16 + ((quad >> 1) & 1) * 8 + (lane & 7);
                const int colB = ks + (quad & 1) * 8;
                const uint32_t ad = sa + (uint32_t)(rowB * ROWB + colB * 2);
                ldmx4(ad + SM_BH, bh[2 * p][0], bh[2 * p][1], bh[2 * p + 1][0], bh[2 * p + 1][1]);
                ldmx4(ad + SM_BL, bl[2 * p][0], bl[2 * p][1], bl[2 * p + 1][0], bl[2 * p + 1][1]);
            }
            #pragma unroll
            for (int mf = 0; mf < 4; mf++) {
                const int rowA = m_off + mf * 16 + (lane & 15);
                const int colA = ks + ((lane >> 4) & 1) * 8;
                const uint32_t ad = sa + (uint32_t)(rowA * ROWB + colA * 2);
                uint32_t ah[4], al[4];
                ldmx4(ad + SM_AH, ah[0], ah[1], ah[2], ah[3]);
                ldmx4(ad + SM_AL, al[0], al[1], al[2], al[3]);
                #pragma unroll
                for (int nf = 0; nf < 4; nf++) {
                    mma_bf16(acc[mf][nf], ah, bh[nf]);
                    mma_bf16(acc[mf][nf], ah, bl[nf]);
                    mma_bf16(acc[mf][nf], al, bh[nf]);
                }
            }
        }
        __syncthreads();
    }

    // ---- epilogue: + bias, direct float2 stores ----
    float* Out = out + (size_t)n_sel * N_PTS * C_OUT + (size_t)m0 * C_OUT;
    const int r4 = lane >> 2;
    const int c2 = (lane & 3) * 2;
    #pragma unroll
    for (int mf = 0; mf < 4; mf++) {
        #pragma unroll
        for (int nf = 0; nf < 4; nf++) {
            const int col  = n_off + nf * 8 + c2;
            const int gcol = n_base + col;
            const float bx = bs[col], by = bs[col + 1];
            const int row0 = m_off + mf * 16 + r4;
            float2 o0, o1;
            o0.x = acc[mf][nf][0] + bx; o0.y = acc[mf][nf][1] + by;
            o1.x = acc[mf][nf][2] + bx; o1.y = acc[mf][nf][3] + by;
            *reinterpret_cast<float2*>(Out + (size_t)row0 * C_OUT + gcol) = o0;
            *reinterpret_cast<float2*>(Out + (size_t)(row0 + 8) * C_OUT + gcol) = o1;
        }
    }
}

extern "C" void kernel_launch(void* const* d_in, const int* in_sizes, int n_in,
                              void* d_out, int out_size) {
    const float* x       = (const float*)d_in[0];
    const float* weight  = (const float*)d_in[1];
    const float* bias    = (const float*)d_in[2];
    const int*   indices = (const int*)d_in[3];
    const int*   t_ptr   = (n_in > 4) ? (const int*)d_in[4] : nullptr;
    float*       out     = (float*)d_out;

    {
        dim3 grid(C_OUT / 32, C_IN / 32, N_SEL);
        dim3 block(32, 8);
        wt_prep_kernel<<<grid, block>>>(weight, indices, t_ptr);
    }
    {
        dim3 grid(N_PTS / BM, C_OUT / BN, N_SEL);   // (16, 2, 192)
        dim3 block(256);
        gemm_bf16_kernel<<<grid, block>>>(x, bias, indices, t_ptr, out);
    }
}